// round 8
// baseline (speedup 1.0000x reference)
#include <cuda_runtime.h>
#include <cuda_bf16.h>
#include <cstdint>
#include <cstddef>

#define NNODES 50000
#define NEDGES 800000
#define DIM 64
#define ETILES (NEDGES / 16)    // 50000
#define NTILES (NNODES / 16)    // 3125
#define WPB 12                  // warps per block (384 threads)

__device__ float g_node_x[NNODES * DIM];
__device__ float g_y[NNODES * DIM];      // node_x @ W1 + 0.5*b1
__device__ int   g_is64;

// pack two fp32 -> bf16x2 (bits[15:0]=first elem, bits[31:16]=second elem)
__device__ __forceinline__ uint32_t bf2(float lo, float hi) {
    uint32_t r;
    asm("cvt.rn.bf16x2.f32 %0, %1, %2;" : "=r"(r) : "f"(hi), "f"(lo));
    return r;
}
__device__ __forceinline__ uint32_t bf2lo(uint32_t h, float x, float y) {
    return bf2(x - __uint_as_float(h << 16), y - __uint_as_float(h & 0xFFFF0000u));
}
__device__ __forceinline__ void mma_bf16(float* d, const uint32_t* a, uint32_t b0, uint32_t b1) {
    asm volatile(
        "mma.sync.aligned.m16n8k16.row.col.f32.bf16.bf16.f32 "
        "{%0,%1,%2,%3}, {%4,%5,%6,%7}, {%8,%9}, {%0,%1,%2,%3};"
        : "+f"(d[0]), "+f"(d[1]), "+f"(d[2]), "+f"(d[3])
        : "r"(a[0]), "r"(a[1]), "r"(a[2]), "r"(a[3]), "r"(b0), "r"(b1));
}

// ---------------- small kernels ----------------
__global__ void detect_kernel(const int* __restrict__ src) {
    if (threadIdx.x == 0) {
        int z = 1;
        #pragma unroll
        for (int i = 0; i < 32; i++) z &= (src[2 * i + 1] == 0);
        g_is64 = z;
    }
}

__global__ void zero_kernel() {
    int i = blockIdx.x * blockDim.x + threadIdx.x;
    float4* p = (float4*)g_node_x;
    if (i < NNODES * DIM / 4) p[i] = make_float4(0.f, 0.f, 0.f, 0.f);
}

__global__ void scatter_kernel(const float4* __restrict__ ef, const void* __restrict__ dstp) {
    int t = blockIdx.x * blockDim.x + threadIdx.x;
    if (t >= NEDGES * (DIM / 4)) return;
    int e = t >> 4;
    int q = t & 15;
    long long d = g_is64 ? ((const long long*)dstp)[e]
                         : (long long)((const int*)dstp)[e];
    float4 v = ef[t];
    float* addr = g_node_x + d * DIM + q * 4;
    asm volatile("red.global.add.v4.f32 [%0], {%1, %2, %3, %4};"
                 :: "l"(addr), "f"(v.x), "f"(v.y), "f"(v.z), "f"(v.w) : "memory");
}

// ---------------- gather stage (raw, pre-relu) ----------------
template <bool EDGE>
__device__ __forceinline__ void gather_tile(
    const void* __restrict__ srcp, const void* __restrict__ dstp, int is64,
    int tile, int g, int tg, const float* __restrict__ Abase,
    float2* A0, float2* A1, float2* A2, float2* A3,
    float2* B0, float2* B1, float2* B2, float2* B3)
{
    const int r0 = tile * 16 + g, r1 = r0 + 8;
    const float *pa0, *pa1, *pb0 = nullptr, *pb1 = nullptr;
    if (EDGE) {
        long long s0, d0, s1, d1;
        if (is64) {
            s0 = ((const long long*)srcp)[r0]; d0 = ((const long long*)dstp)[r0];
            s1 = ((const long long*)srcp)[r1]; d1 = ((const long long*)dstp)[r1];
        } else {
            s0 = ((const int*)srcp)[r0]; d0 = ((const int*)dstp)[r0];
            s1 = ((const int*)srcp)[r1]; d1 = ((const int*)dstp)[r1];
        }
        pa0 = Abase + s0 * DIM; pb0 = Abase + d0 * DIM;
        pa1 = Abase + s1 * DIM; pb1 = Abase + d1 * DIM;
    } else {
        pa0 = Abase + (long long)r0 * DIM;
        pa1 = Abase + (long long)r1 * DIM;
    }
    #pragma unroll
    for (int ks = 0; ks < 4; ks++) {
        const int c0 = ks * 16 + 2 * tg;
        A0[ks] = *(const float2*)(pa0 + c0);
        A1[ks] = *(const float2*)(pa0 + c0 + 8);
        A2[ks] = *(const float2*)(pa1 + c0);
        A3[ks] = *(const float2*)(pa1 + c0 + 8);
        if (EDGE) {
            B0[ks] = *(const float2*)(pb0 + c0);
            B1[ks] = *(const float2*)(pb0 + c0 + 8);
            B2[ks] = *(const float2*)(pb1 + c0);
            B3[ks] = *(const float2*)(pb1 + c0 + 8);
        }
    }
}

// ---------------- HMMA MLP kernel (B in smem, pipelined gathers) ----------------
// EDGE=false: y[row]   = node_x[row] @ W1 + 0.5*b1
// EDGE=true : out[row] = 0.5*(relu(y[src]+y[dst]) @ W2) + 0.5*b2
template <bool EDGE>
__global__ void __launch_bounds__(32 * WPB, 1) mlp_kernel(
    const void* __restrict__ srcp, const void* __restrict__ dstp,
    const float* __restrict__ W, const float* __restrict__ bias,
    float* __restrict__ outp, int ntiles)
{
    __shared__ uint2 sBhi[8][4][32];
    __shared__ uint2 sBlo[8][4][32];
    __shared__ float sBias[64];

    const int tid = threadIdx.x;
    const int warp = tid >> 5, lane = tid & 31;
    const int g = lane >> 2, tg = lane & 3;
    const int is64 = EDGE ? g_is64 : 0;
    const float* __restrict__ Abase = EDGE ? g_y : g_node_x;
    float* __restrict__ out = EDGE ? outp : g_y;
    constexpr float SC = EDGE ? 0.5f : 1.0f;

    // build B fragments in smem: n = nt*8+g, k = ks*16 + 2*tg + 8*hx
    for (int idx = tid; idx < 1024; idx += 32 * WPB) {
        int l = idx & 31, ks = (idx >> 5) & 3, nt = idx >> 7;
        int gg = l >> 2, tt = l & 3;
        int n = nt * 8 + gg;
        int k0 = ks * 16 + 2 * tt;
        float w0 = W[k0 * DIM + n],       w1 = W[(k0 + 1) * DIM + n];
        float w2 = W[(k0 + 8) * DIM + n], w3 = W[(k0 + 9) * DIM + n];
        uint32_t h0 = bf2(w0, w1), h1 = bf2(w2, w3);
        sBhi[nt][ks][l] = make_uint2(h0, h1);
        sBlo[nt][ks][l] = make_uint2(bf2lo(h0, w0, w1), bf2lo(h1, w2, w3));
    }
    if (tid < 64) sBias[tid] = 0.5f * bias[tid];
    __syncthreads();

    const int gw = blockIdx.x * WPB + warp;
    const int nw = gridDim.x * WPB;
    if (gw >= ntiles) return;

    float2 A0[4], A1[4], A2[4], A3[4], B0[4], B1[4], B2[4], B3[4];
    gather_tile<EDGE>(srcp, dstp, is64, gw, g, tg, Abase, A0, A1, A2, A3, B0, B1, B2, B3);

    for (int tile = gw; tile < ntiles; ) {
        // ---- combine + convert (consumes in-flight gathers) ----
        uint32_t ahi[4][4], alo[4][4];
        #pragma unroll
        for (int ks = 0; ks < 4; ks++) {
            float2 h00, h01, h10, h11;
            if (EDGE) {
                h00 = make_float2(fmaxf(A0[ks].x + B0[ks].x, 0.f), fmaxf(A0[ks].y + B0[ks].y, 0.f));
                h01 = make_float2(fmaxf(A1[ks].x + B1[ks].x, 0.f), fmaxf(A1[ks].y + B1[ks].y, 0.f));
                h10 = make_float2(fmaxf(A2[ks].x + B2[ks].x, 0.f), fmaxf(A2[ks].y + B2[ks].y, 0.f));
                h11 = make_float2(fmaxf(A3[ks].x + B3[ks].x, 0.f), fmaxf(A3[ks].y + B3[ks].y, 0.f));
            } else {
                h00 = A0[ks]; h01 = A1[ks]; h10 = A2[ks]; h11 = A3[ks];
            }
            ahi[ks][0] = bf2(h00.x, h00.y);  alo[ks][0] = bf2lo(ahi[ks][0], h00.x, h00.y);
            ahi[ks][1] = bf2(h10.x, h10.y);  alo[ks][1] = bf2lo(ahi[ks][1], h10.x, h10.y);
            ahi[ks][2] = bf2(h01.x, h01.y);  alo[ks][2] = bf2lo(ahi[ks][2], h01.x, h01.y);
            ahi[ks][3] = bf2(h11.x, h11.y);  alo[ks][3] = bf2lo(ahi[ks][3], h11.x, h11.y);
        }

        // ---- prefetch next tile's gathers (consumed next iteration) ----
        const int next = tile + nw;
        const int pf = (next < ntiles) ? next : tile;
        gather_tile<EDGE>(srcp, dstp, is64, pf, g, tg, Abase, A0, A1, A2, A3, B0, B1, B2, B3);

        // ---- mma: D = Ahi*Bhi + Alo*Bhi + Ahi*Blo ----
        float acc[8][4];
        #pragma unroll
        for (int nt = 0; nt < 8; nt++) {
            acc[nt][0] = 0.f; acc[nt][1] = 0.f; acc[nt][2] = 0.f; acc[nt][3] = 0.f;
        }
        #pragma unroll
        for (int nt = 0; nt < 8; nt++) {
            #pragma unroll
            for (int ks = 0; ks < 4; ks++) {
                uint2 bh = sBhi[nt][ks][lane];
                uint2 bl = sBlo[nt][ks][lane];
                mma_bf16(acc[nt], ahi[ks], bh.x, bh.y);
                mma_bf16(acc[nt], alo[ks], bh.x, bh.y);
                mma_bf16(acc[nt], ahi[ks], bl.x, bl.y);
            }
        }

        // ---- epilogue ----
        const int r0 = tile * 16 + g;
        float* o0 = out + (long long)r0 * DIM;
        float* o1 = o0 + 8 * DIM;
        #pragma unroll
        for (int nt = 0; nt < 8; nt++) {
            float2 bb = *(const float2*)(sBias + nt * 8 + 2 * tg);
            *(float2*)(o0 + nt * 8 + 2 * tg) =
                make_float2(SC * acc[nt][0] + bb.x, SC * acc[nt][1] + bb.y);
            *(float2*)(o1 + nt * 8 + 2 * tg) =
                make_float2(SC * acc[nt][2] + bb.x, SC * acc[nt][3] + bb.y);
        }
        tile = next;
    }
}

// ---------------- launch ----------------
extern "C" void kernel_launch(void* const* d_in, const int* in_sizes, int n_in,
                              void* d_out, int out_size) {
    const float4* edge_feat = (const float4*)d_in[0];
    const void*   src       = d_in[1];
    const void*   dst       = d_in[2];
    const float*  W1        = (const float*)d_in[3];
    const float*  b1        = (const float*)d_in[4];
    const float*  W2        = (const float*)d_in[5];
    const float*  b2        = (const float*)d_in[6];
    float*        out       = (float*)d_out;

    detect_kernel<<<1, 32>>>((const int*)src);
    zero_kernel<<<(NNODES * DIM / 4 + 255) / 256, 256>>>();
    scatter_kernel<<<(NEDGES * 16 + 255) / 256, 256>>>(edge_feat, dst);
    mlp_kernel<false><<<148, 32 * WPB>>>(nullptr, nullptr, W1, b1, nullptr, NTILES);
    mlp_kernel<true><<<148, 32 * WPB>>>(src, dst, W2, b2, out, ETILES);
}

// round 9
// speedup vs baseline: 1.2944x; 1.2944x over previous
#include <cuda_runtime.h>
#include <cuda_bf16.h>
#include <cstdint>
#include <cstddef>

#define NNODES 50000
#define NEDGES 800000
#define DIM 64
#define ETILES (NEDGES / 16)    // 50000
#define NTILES (NNODES / 16)    // 3125
#define SCAN_NB 196             // 196*256 >= 50000

__device__ float g_node_x[NNODES * DIM];
__device__ float g_y[NNODES * DIM];
__device__ int   g_is64;
__device__ int   g_cnt[SCAN_NB * 256];
__device__ int   g_off[NNODES + 1];
__device__ int   g_cur[NNODES];
__device__ int   g_perm[NEDGES];
__device__ int   g_bsum[SCAN_NB];
__device__ int   g_bpre[SCAN_NB];

// ---------------- bf16 helpers ----------------
__device__ __forceinline__ uint32_t bf2(float lo, float hi) {
    uint32_t r;
    asm("cvt.rn.bf16x2.f32 %0, %1, %2;" : "=r"(r) : "f"(hi), "f"(lo));
    return r;
}
__device__ __forceinline__ uint32_t bf2lo(uint32_t h, float x, float y) {
    return bf2(x - __uint_as_float(h << 16), y - __uint_as_float(h & 0xFFFF0000u));
}
__device__ __forceinline__ void mma_bf16(float* d, const uint32_t* a, const uint32_t* b) {
    asm volatile(
        "mma.sync.aligned.m16n8k16.row.col.f32.bf16.bf16.f32 "
        "{%0,%1,%2,%3}, {%4,%5,%6,%7}, {%8,%9}, {%0,%1,%2,%3};"
        : "+f"(d[0]), "+f"(d[1]), "+f"(d[2]), "+f"(d[3])
        : "r"(a[0]), "r"(a[1]), "r"(a[2]), "r"(a[3]), "r"(b[0]), "r"(b[1]));
}

__device__ __forceinline__ long long load_idx(const void* p, int e, int is64) {
    return is64 ? ((const long long*)p)[e] : (long long)((const int*)p)[e];
}

// ---------------- setup kernels ----------------
__global__ void detect_kernel(const int* __restrict__ src) {
    if (threadIdx.x == 0) {
        int z = 1;
        #pragma unroll
        for (int i = 0; i < 32; i++) z &= (src[2 * i + 1] == 0);
        g_is64 = z;
    }
}

__global__ void zero_cnt_kernel() {
    int i = blockIdx.x * blockDim.x + threadIdx.x;
    if (i < SCAN_NB * 256) g_cnt[i] = 0;
}

__global__ void hist_kernel(const void* __restrict__ dstp) {
    int e = blockIdx.x * blockDim.x + threadIdx.x;
    if (e >= NEDGES) return;
    int d = (int)load_idx(dstp, e, g_is64);
    atomicAdd(&g_cnt[d], 1);
}

// block sums of counts
__global__ void scan1_kernel() {
    __shared__ int sm[256];
    int i = blockIdx.x * 256 + threadIdx.x;
    sm[threadIdx.x] = g_cnt[i];
    __syncthreads();
    for (int s = 128; s > 0; s >>= 1) {
        if (threadIdx.x < s) sm[threadIdx.x] += sm[threadIdx.x + s];
        __syncthreads();
    }
    if (threadIdx.x == 0) g_bsum[blockIdx.x] = sm[0];
}

// serial exclusive scan over SCAN_NB block sums
__global__ void scan2_kernel() {
    if (threadIdx.x == 0) {
        int acc = 0;
        for (int b = 0; b < SCAN_NB; b++) { g_bpre[b] = acc; acc += g_bsum[b]; }
        g_off[NNODES] = NEDGES;
    }
}

// in-block exclusive scan + base; write g_off and g_cur
__global__ void scan3_kernel() {
    __shared__ int wsum[8];
    int i = blockIdx.x * 256 + threadIdx.x;
    int lane = threadIdx.x & 31, warp = threadIdx.x >> 5;
    int c = g_cnt[i];
    int v = c;
    #pragma unroll
    for (int s = 1; s < 32; s <<= 1) {
        int t = __shfl_up_sync(0xFFFFFFFF, v, s);
        if (lane >= s) v += t;
    }
    if (lane == 31) wsum[warp] = v;
    __syncthreads();
    if (warp == 0 && lane < 8) {
        int w = wsum[lane];
        #pragma unroll
        for (int s = 1; s < 8; s <<= 1) {
            int t = __shfl_up_sync(0xFF, w, s);
            if (lane >= s) w += t;
        }
        wsum[lane] = w;
    }
    __syncthreads();
    int excl = v - c + (warp ? wsum[warp - 1] : 0) + g_bpre[blockIdx.x];
    if (i < NNODES) { g_off[i] = excl; g_cur[i] = excl; }
}

__global__ void permute_kernel(const void* __restrict__ dstp) {
    int e = blockIdx.x * blockDim.x + threadIdx.x;
    if (e >= NEDGES) return;
    int d = (int)load_idx(dstp, e, g_is64);
    int pos = atomicAdd(&g_cur[d], 1);
    g_perm[pos] = e;
}

// one warp per node: node_x[v] = sum of edge_feat rows (coalesced, no fp atomics)
__global__ void __launch_bounds__(256) nodesum_kernel(const float2* __restrict__ ef2) {
    int v = blockIdx.x * 8 + (threadIdx.x >> 5);
    if (v >= NNODES) return;
    int lane = threadIdx.x & 31;
    int beg = g_off[v], end = g_off[v + 1];
    float2 acc = make_float2(0.f, 0.f);
    int j = beg;
    for (; j + 1 < end; j += 2) {
        int e0 = g_perm[j], e1 = g_perm[j + 1];
        float2 t0 = ef2[(size_t)e0 * 32 + lane];
        float2 t1 = ef2[(size_t)e1 * 32 + lane];
        acc.x += t0.x + t1.x;
        acc.y += t0.y + t1.y;
    }
    if (j < end) {
        float2 t = ef2[(size_t)g_perm[j] * 32 + lane];
        acc.x += t.x; acc.y += t.y;
    }
    ((float2*)(g_node_x + (size_t)v * DIM))[lane] = acc;
}

// ---------------- HMMA MLP kernel (R7 verbatim: B in registers) ----------------
template <bool EDGE>
__global__ void __launch_bounds__(256, 1) mlp_kernel(
    const void* __restrict__ srcp, const void* __restrict__ dstp,
    const float* __restrict__ W, const float* __restrict__ bias,
    float* __restrict__ outp, int ntiles)
{
    const int tid = threadIdx.x;
    const int warp = tid >> 5, lane = tid & 31;
    const int g = lane >> 2, tg = lane & 3;
    const int is64 = EDGE ? g_is64 : 0;
    const float* __restrict__ Abase = EDGE ? g_y : g_node_x;
    float* __restrict__ out = EDGE ? outp : g_y;
    constexpr float SC = EDGE ? 0.5f : 1.0f;

    uint32_t Bhi[8][4][2], Blo[8][4][2];
    #pragma unroll
    for (int nt = 0; nt < 8; nt++) {
        int n = nt * 8 + g;
        #pragma unroll
        for (int ks = 0; ks < 4; ks++) {
            #pragma unroll
            for (int hx = 0; hx < 2; hx++) {
                int k = ks * 16 + 2 * tg + 8 * hx;
                float w0 = W[k * DIM + n];
                float w1 = W[(k + 1) * DIM + n];
                uint32_t h = bf2(w0, w1);
                Bhi[nt][ks][hx] = h;
                Blo[nt][ks][hx] = bf2lo(h, w0, w1);
            }
        }
    }

    const int gw = blockIdx.x * 8 + warp;
    const int nw = gridDim.x * 8;
    for (int tile = gw; tile < ntiles; tile += nw) {
        const int r0 = tile * 16 + g;
        const int r1 = r0 + 8;

        const float *p0a, *p0b = nullptr, *p1a, *p1b = nullptr;
        if (EDGE) {
            long long s0 = load_idx(srcp, r0, is64), d0 = load_idx(dstp, r0, is64);
            long long s1 = load_idx(srcp, r1, is64), d1 = load_idx(dstp, r1, is64);
            p0a = Abase + s0 * DIM; p0b = Abase + d0 * DIM;
            p1a = Abase + s1 * DIM; p1b = Abase + d1 * DIM;
        } else {
            p0a = Abase + (long long)r0 * DIM;
            p1a = Abase + (long long)r1 * DIM;
        }

        float acc[8][4];
        #pragma unroll
        for (int nt = 0; nt < 8; nt++) {
            acc[nt][0] = 0.f; acc[nt][1] = 0.f; acc[nt][2] = 0.f; acc[nt][3] = 0.f;
        }

        #pragma unroll
        for (int ks = 0; ks < 4; ks++) {
            const int c0 = ks * 16 + 2 * tg;
            float2 h00, h01, h10, h11;
            if (EDGE) {
                float2 a, b;
                a = *(const float2*)(p0a + c0);     b = *(const float2*)(p0b + c0);
                h00 = make_float2(fmaxf(a.x + b.x, 0.f), fmaxf(a.y + b.y, 0.f));
                a = *(const float2*)(p0a + c0 + 8); b = *(const float2*)(p0b + c0 + 8);
                h01 = make_float2(fmaxf(a.x + b.x, 0.f), fmaxf(a.y + b.y, 0.f));
                a = *(const float2*)(p1a + c0);     b = *(const float2*)(p1b + c0);
                h10 = make_float2(fmaxf(a.x + b.x, 0.f), fmaxf(a.y + b.y, 0.f));
                a = *(const float2*)(p1a + c0 + 8); b = *(const float2*)(p1b + c0 + 8);
                h11 = make_float2(fmaxf(a.x + b.x, 0.f), fmaxf(a.y + b.y, 0.f));
            } else {
                h00 = *(const float2*)(p0a + c0);
                h01 = *(const float2*)(p0a + c0 + 8);
                h10 = *(const float2*)(p1a + c0);
                h11 = *(const float2*)(p1a + c0 + 8);
            }
            uint32_t ahi[4], alo[4];
            ahi[0] = bf2(h00.x, h00.y);  alo[0] = bf2lo(ahi[0], h00.x, h00.y);
            ahi[1] = bf2(h10.x, h10.y);  alo[1] = bf2lo(ahi[1], h10.x, h10.y);
            ahi[2] = bf2(h01.x, h01.y);  alo[2] = bf2lo(ahi[2], h01.x, h01.y);
            ahi[3] = bf2(h11.x, h11.y);  alo[3] = bf2lo(ahi[3], h11.x, h11.y);

            #pragma unroll
            for (int nt = 0; nt < 8; nt++) {
                mma_bf16(acc[nt], ahi, Bhi[nt][ks]);
                mma_bf16(acc[nt], alo, Bhi[nt][ks]);
                mma_bf16(acc[nt], ahi, Blo[nt][ks]);
            }
        }

        float* o0 = out + (long long)r0 * DIM;
        float* o1 = out + (long long)r1 * DIM;
        #pragma unroll
        for (int nt = 0; nt < 8; nt++) {
            float2 bb = *(const float2*)(bias + nt * 8 + 2 * tg);
            *(float2*)(o0 + nt * 8 + 2 * tg) =
                make_float2(SC * acc[nt][0] + 0.5f * bb.x, SC * acc[nt][1] + 0.5f * bb.y);
            *(float2*)(o1 + nt * 8 + 2 * tg) =
                make_float2(SC * acc[nt][2] + 0.5f * bb.x, SC * acc[nt][3] + 0.5f * bb.y);
        }
    }
}

// ---------------- launch ----------------
extern "C" void kernel_launch(void* const* d_in, const int* in_sizes, int n_in,
                              void* d_out, int out_size) {
    const float2* edge_feat = (const float2*)d_in[0];
    const void*   src       = d_in[1];
    const void*   dst       = d_in[2];
    const float*  W1        = (const float*)d_in[3];
    const float*  b1        = (const float*)d_in[4];
    const float*  W2        = (const float*)d_in[5];
    const float*  b2        = (const float*)d_in[6];
    float*        out       = (float*)d_out;

    detect_kernel<<<1, 32>>>((const int*)src);
    zero_cnt_kernel<<<SCAN_NB, 256>>>();
    hist_kernel<<<(NEDGES + 255) / 256, 256>>>(dst);
    scan1_kernel<<<SCAN_NB, 256>>>();
    scan2_kernel<<<1, 32>>>();
    scan3_kernel<<<SCAN_NB, 256>>>();
    permute_kernel<<<(NEDGES + 255) / 256, 256>>>(dst);
    nodesum_kernel<<<(NNODES + 7) / 8, 256>>>(edge_feat);
    mlp_kernel<false><<<148, 256>>>(nullptr, nullptr, W1, b1, nullptr, NTILES);
    mlp_kernel<true><<<148, 256>>>(src, dst, W2, b2, out, ETILES);
}

// round 10
// speedup vs baseline: 1.5554x; 1.2017x over previous
#include <cuda_runtime.h>
#include <cuda_bf16.h>
#include <cstdint>
#include <cstddef>

#define NNODES 50000
#define NEDGES 800000
#define DIM 64
#define ETILES (NEDGES / 16)    // 50000
#define NTILES (NNODES / 16)    // 3125

__device__ float g_node_x[NNODES * DIM];
__device__ float g_y[NNODES * DIM];      // node_x @ W1 + 0.5*b1
__device__ int   g_is64;

// pack two fp32 -> bf16x2
__device__ __forceinline__ uint32_t bf2(float lo, float hi) {
    uint32_t r;
    asm("cvt.rn.bf16x2.f32 %0, %1, %2;" : "=r"(r) : "f"(hi), "f"(lo));
    return r;
}
__device__ __forceinline__ uint32_t bf2lo(uint32_t h, float x, float y) {
    return bf2(x - __uint_as_float(h << 16), y - __uint_as_float(h & 0xFFFF0000u));
}
__device__ __forceinline__ void mma_bf16(float* d, const uint32_t* a, const uint32_t* b) {
    asm volatile(
        "mma.sync.aligned.m16n8k16.row.col.f32.bf16.bf16.f32 "
        "{%0,%1,%2,%3}, {%4,%5,%6,%7}, {%8,%9}, {%0,%1,%2,%3};"
        : "+f"(d[0]), "+f"(d[1]), "+f"(d[2]), "+f"(d[3])
        : "r"(a[0]), "r"(a[1]), "r"(a[2]), "r"(a[3]), "r"(b[0]), "r"(b[1]));
}
__device__ __forceinline__ long long load_idx(const void* p, int e, int is64) {
    return is64 ? ((const long long*)p)[e] : (long long)((const int*)p)[e];
}

// ---------------- fused zero + dtype-detect ----------------
__global__ void zero_detect_kernel(const int* __restrict__ src) {
    int i = blockIdx.x * blockDim.x + threadIdx.x;
    if (i < NNODES * DIM / 4)
        ((float4*)g_node_x)[i] = make_float4(0.f, 0.f, 0.f, 0.f);
    if (i == 0) {
        int z = 1;
        #pragma unroll
        for (int k = 0; k < 32; k++) z &= (src[2 * k + 1] == 0);
        g_is64 = z;
    }
}

// ---------------- scatter: node_x[dst] += edge_feat ----------------
__global__ void scatter_kernel(const float4* __restrict__ ef, const void* __restrict__ dstp) {
    int t = blockIdx.x * blockDim.x + threadIdx.x;
    if (t >= NEDGES * (DIM / 4)) return;
    int e = t >> 4;
    int q = t & 15;
    long long d = g_is64 ? ((const long long*)dstp)[e]
                         : (long long)((const int*)dstp)[e];
    float4 v = __ldcs(ef + t);                 // streaming read, evict-first
    float* addr = g_node_x + d * DIM + q * 4;
    asm volatile("red.global.add.v4.f32 [%0], {%1, %2, %3, %4};"
                 :: "l"(addr), "f"(v.x), "f"(v.y), "f"(v.z), "f"(v.w) : "memory");
}

// ---------------- HMMA MLP kernel (B in registers; idx prefetch; stcs out) ----------------
// EDGE=false: y[row]   = node_x[row] @ W1 + 0.5*b1
// EDGE=true : out[row] = 0.5*(relu(y[src]+y[dst]) @ W2) + 0.5*b2
template <bool EDGE>
__global__ void __launch_bounds__(256, 1) mlp_kernel(
    const void* __restrict__ srcp, const void* __restrict__ dstp,
    const float* __restrict__ W, const float* __restrict__ bias,
    float* __restrict__ outp, int ntiles)
{
    const int tid = threadIdx.x;
    const int warp = tid >> 5, lane = tid & 31;
    const int g = lane >> 2, tg = lane & 3;
    const int is64 = EDGE ? g_is64 : 0;
    const float* __restrict__ Abase = EDGE ? g_y : g_node_x;
    float* __restrict__ out = EDGE ? outp : g_y;
    constexpr float SC = EDGE ? 0.5f : 1.0f;

    uint32_t Bhi[8][4][2], Blo[8][4][2];
    #pragma unroll
    for (int nt = 0; nt < 8; nt++) {
        int n = nt * 8 + g;
        #pragma unroll
        for (int ks = 0; ks < 4; ks++) {
            #pragma unroll
            for (int hx = 0; hx < 2; hx++) {
                int k = ks * 16 + 2 * tg + 8 * hx;
                float w0 = W[k * DIM + n];
                float w1 = W[(k + 1) * DIM + n];
                uint32_t h = bf2(w0, w1);
                Bhi[nt][ks][hx] = h;
                Blo[nt][ks][hx] = bf2lo(h, w0, w1);
            }
        }
    }

    const int gw = blockIdx.x * 8 + warp;
    const int nw = gridDim.x * 8;
    if (gw >= ntiles) return;

    // prefetched indices for the current tile (EDGE only)
    long long s0 = 0, d0 = 0, s1 = 0, d1 = 0;
    if (EDGE) {
        s0 = load_idx(srcp, gw * 16 + g, is64);
        d0 = load_idx(dstp, gw * 16 + g, is64);
        s1 = load_idx(srcp, gw * 16 + g + 8, is64);
        d1 = load_idx(dstp, gw * 16 + g + 8, is64);
    }

    for (int tile = gw; tile < ntiles; tile += nw) {
        const int r0 = tile * 16 + g;
        const int r1 = r0 + 8;

        const float *p0a, *p0b = nullptr, *p1a, *p1b = nullptr;
        if (EDGE) {
            p0a = Abase + s0 * DIM; p0b = Abase + d0 * DIM;
            p1a = Abase + s1 * DIM; p1b = Abase + d1 * DIM;
        } else {
            p0a = Abase + (long long)r0 * DIM;
            p1a = Abase + (long long)r1 * DIM;
        }

        // prefetch next tile's indices (hidden behind gathers + MMA)
        if (EDGE) {
            const int tn = tile + nw;
            if (tn < ntiles) {
                const int rn0 = tn * 16 + g, rn1 = rn0 + 8;
                s0 = load_idx(srcp, rn0, is64);
                d0 = load_idx(dstp, rn0, is64);
                s1 = load_idx(srcp, rn1, is64);
                d1 = load_idx(dstp, rn1, is64);
            }
        }

        float acc[8][4];
        #pragma unroll
        for (int nt = 0; nt < 8; nt++) {
            acc[nt][0] = 0.f; acc[nt][1] = 0.f; acc[nt][2] = 0.f; acc[nt][3] = 0.f;
        }

        #pragma unroll
        for (int ks = 0; ks < 4; ks++) {
            const int c0 = ks * 16 + 2 * tg;
            float2 h00, h01, h10, h11;
            if (EDGE) {
                float2 a, b;
                a = *(const float2*)(p0a + c0);     b = *(const float2*)(p0b + c0);
                h00 = make_float2(fmaxf(a.x + b.x, 0.f), fmaxf(a.y + b.y, 0.f));
                a = *(const float2*)(p0a + c0 + 8); b = *(const float2*)(p0b + c0 + 8);
                h01 = make_float2(fmaxf(a.x + b.x, 0.f), fmaxf(a.y + b.y, 0.f));
                a = *(const float2*)(p1a + c0);     b = *(const float2*)(p1b + c0);
                h10 = make_float2(fmaxf(a.x + b.x, 0.f), fmaxf(a.y + b.y, 0.f));
                a = *(const float2*)(p1a + c0 + 8); b = *(const float2*)(p1b + c0 + 8);
                h11 = make_float2(fmaxf(a.x + b.x, 0.f), fmaxf(a.y + b.y, 0.f));
            } else {
                h00 = *(const float2*)(p0a + c0);
                h01 = *(const float2*)(p0a + c0 + 8);
                h10 = *(const float2*)(p1a + c0);
                h11 = *(const float2*)(p1a + c0 + 8);
            }
            uint32_t ahi[4], alo[4];
            ahi[0] = bf2(h00.x, h00.y);  alo[0] = bf2lo(ahi[0], h00.x, h00.y);
            ahi[1] = bf2(h10.x, h10.y);  alo[1] = bf2lo(ahi[1], h10.x, h10.y);
            ahi[2] = bf2(h01.x, h01.y);  alo[2] = bf2lo(ahi[2], h01.x, h01.y);
            ahi[3] = bf2(h11.x, h11.y);  alo[3] = bf2lo(ahi[3], h11.x, h11.y);

            #pragma unroll
            for (int nt = 0; nt < 8; nt++) {
                mma_bf16(acc[nt], ahi, Bhi[nt][ks]);
                mma_bf16(acc[nt], alo, Bhi[nt][ks]);
                mma_bf16(acc[nt], ahi, Blo[nt][ks]);
            }
        }

        float* o0 = out + (long long)r0 * DIM;
        float* o1 = out + (long long)r1 * DIM;
        #pragma unroll
        for (int nt = 0; nt < 8; nt++) {
            float2 bb = *(const float2*)(bias + nt * 8 + 2 * tg);
            float2 v0 = make_float2(SC * acc[nt][0] + 0.5f * bb.x,
                                    SC * acc[nt][1] + 0.5f * bb.y);
            float2 v1 = make_float2(SC * acc[nt][2] + 0.5f * bb.x,
                                    SC * acc[nt][3] + 0.5f * bb.y);
            if (EDGE) {
                __stcs((float2*)(o0 + nt * 8 + 2 * tg), v0);   // streaming store
                __stcs((float2*)(o1 + nt * 8 + 2 * tg), v1);
            } else {
                *(float2*)(o0 + nt * 8 + 2 * tg) = v0;
                *(float2*)(o1 + nt * 8 + 2 * tg) = v1;
            }
        }
    }
}

// ---------------- launch ----------------
extern "C" void kernel_launch(void* const* d_in, const int* in_sizes, int n_in,
                              void* d_out, int out_size) {
    const float4* edge_feat = (const float4*)d_in[0];
    const void*   src       = d_in[1];
    const void*   dst       = d_in[2];
    const float*  W1        = (const float*)d_in[3];
    const float*  b1        = (const float*)d_in[4];
    const float*  W2        = (const float*)d_in[5];
    const float*  b2        = (const float*)d_in[6];
    float*        out       = (float*)d_out;

    zero_detect_kernel<<<(NNODES * DIM / 4 + 255) / 256, 256>>>((const int*)src);
    scatter_kernel<<<(NEDGES * 16 + 255) / 256, 256>>>(edge_feat, dst);
    mlp_kernel<false><<<148, 256>>>(nullptr, nullptr, W1, b1, nullptr, NTILES);
    mlp_kernel<true><<<148, 256>>>(src, dst, W2, b2, out, ETILES);
}

// round 14
// speedup vs baseline: 1.7210x; 1.1064x over previous
#include <cuda_runtime.h>
#include <cuda_bf16.h>
#include <cstdint>
#include <cstddef>

#define NNODES 50000
#define NEDGES 800000
#define DIM 64
#define ETILES (NEDGES / 16)    // 50000
#define NTILES (NNODES / 16)    // 3125

__device__ float g_node_x[NNODES * DIM];
__device__ float g_y[NNODES * DIM];      // node_x @ W1 + 0.5*b1
__device__ int   g_is64;

// pack two fp32 -> bf16x2
__device__ __forceinline__ uint32_t bf2(float lo, float hi) {
    uint32_t r;
    asm("cvt.rn.bf16x2.f32 %0, %1, %2;" : "=r"(r) : "f"(hi), "f"(lo));
    return r;
}
__device__ __forceinline__ uint32_t bf2lo(uint32_t h, float x, float y) {
    return bf2(x - __uint_as_float(h << 16), y - __uint_as_float(h & 0xFFFF0000u));
}
__device__ __forceinline__ void mma_bf16(float* d, const uint32_t* a, const uint32_t* b) {
    asm volatile(
        "mma.sync.aligned.m16n8k16.row.col.f32.bf16.bf16.f32 "
        "{%0,%1,%2,%3}, {%4,%5,%6,%7}, {%8,%9}, {%0,%1,%2,%3};"
        : "+f"(d[0]), "+f"(d[1]), "+f"(d[2]), "+f"(d[3])
        : "r"(a[0]), "r"(a[1]), "r"(a[2]), "r"(a[3]), "r"(b[0]), "r"(b[1]));
}
__device__ __forceinline__ long long load_idx(const void* p, int e, int is64) {
    return is64 ? ((const long long*)p)[e] : (long long)((const int*)p)[e];
}

// ---------------- fused zero + dtype-detect ----------------
__global__ void zero_detect_kernel(const int* __restrict__ src) {
    int i = blockIdx.x * blockDim.x + threadIdx.x;
    if (i < NNODES * DIM / 4)
        ((float4*)g_node_x)[i] = make_float4(0.f, 0.f, 0.f, 0.f);
    if (i == 0) {
        int z = 1;
        #pragma unroll
        for (int k = 0; k < 32; k++) z &= (src[2 * k + 1] == 0);
        g_is64 = z;
    }
}

// ---------------- scatter: node_x[dst] += edge_feat ----------------
__global__ void scatter_kernel(const float4* __restrict__ ef, const void* __restrict__ dstp) {
    int t = blockIdx.x * blockDim.x + threadIdx.x;
    if (t >= NEDGES * (DIM / 4)) return;
    int e = t >> 4;
    int q = t & 15;
    long long d = g_is64 ? ((const long long*)dstp)[e]
                         : (long long)((const int*)dstp)[e];
    float4 v = __ldcs(ef + t);
    float* addr = g_node_x + d * DIM + q * 4;
    asm volatile("red.global.add.v4.f32 [%0], {%1, %2, %3, %4};"
                 :: "l"(addr), "f"(v.x), "f"(v.y), "f"(v.z), "f"(v.w) : "memory");
}

// ---------------- HMMA MLP kernel ----------------
// k-permutation: within each k16 block, MMA k-slot {2t,2t+1} <- data col {4t,4t+1},
// k-slot {2t+8,2t+9} <- data col {4t+2,4t+3}. A loads become one LDG.128 per
// row per block; B (W rows) loads use the same permutation. Contraction order
// is irrelevant, so the result is bit-identical in structure.
// EDGE=false: y[row]   = node_x[row] @ W1 + 0.5*b1
// EDGE=true : out[row] = 0.5*(relu(y[src]+y[dst]) @ W2) + 0.5*b2
template <bool EDGE>
__global__ void __launch_bounds__(256, 1) mlp_kernel(
    const void* __restrict__ srcp, const void* __restrict__ dstp,
    const float* __restrict__ W, const float* __restrict__ bias,
    float* __restrict__ outp, int ntiles)
{
    const int tid = threadIdx.x;
    const int warp = tid >> 5, lane = tid & 31;
    const int g = lane >> 2, tg = lane & 3;
    const int is64 = EDGE ? g_is64 : 0;
    const float* __restrict__ Abase = EDGE ? g_y : g_node_x;
    float* __restrict__ out = EDGE ? outp : g_y;
    constexpr float SC = EDGE ? 0.5f : 1.0f;

    // B fragments with permuted k: slot pair (2t+8hx) <- W rows (ks*16 + 4*tg + 2*hx, +1)
    uint32_t Bhi[8][4][2], Blo[8][4][2];
    #pragma unroll
    for (int nt = 0; nt < 8; nt++) {
        int n = nt * 8 + g;
        #pragma unroll
        for (int ks = 0; ks < 4; ks++) {
            #pragma unroll
            for (int hx = 0; hx < 2; hx++) {
                int k = ks * 16 + 4 * tg + 2 * hx;
                float w0 = W[k * DIM + n];
                float w1 = W[(k + 1) * DIM + n];
                uint32_t h = bf2(w0, w1);
                Bhi[nt][ks][hx] = h;
                Blo[nt][ks][hx] = bf2lo(h, w0, w1);
            }
        }
    }

    const int gw = blockIdx.x * 8 + warp;
    const int nw = gridDim.x * 8;
    if (gw >= ntiles) return;

    long long s0 = 0, d0 = 0, s1 = 0, d1 = 0;
    if (EDGE) {
        s0 = load_idx(srcp, gw * 16 + g, is64);
        d0 = load_idx(dstp, gw * 16 + g, is64);
        s1 = load_idx(srcp, gw * 16 + g + 8, is64);
        d1 = load_idx(dstp, gw * 16 + g + 8, is64);
    }

    for (int tile = gw; tile < ntiles; tile += nw) {
        const int r0 = tile * 16 + g;
        const int r1 = r0 + 8;

        const float *p0a, *p0b = nullptr, *p1a, *p1b = nullptr;
        if (EDGE) {
            p0a = Abase + s0 * DIM; p0b = Abase + d0 * DIM;
            p1a = Abase + s1 * DIM; p1b = Abase + d1 * DIM;
        } else {
            p0a = Abase + (long long)r0 * DIM;
            p1a = Abase + (long long)r1 * DIM;
        }

        if (EDGE) {
            const int tn = tile + nw;
            if (tn < ntiles) {
                const int rn0 = tn * 16 + g, rn1 = rn0 + 8;
                s0 = load_idx(srcp, rn0, is64);
                d0 = load_idx(dstp, rn0, is64);
                s1 = load_idx(srcp, rn1, is64);
                d1 = load_idx(dstp, rn1, is64);
            }
        }

        float acc[8][4];
        #pragma unroll
        for (int nt = 0; nt < 8; nt++) {
            acc[nt][0] = 0.f; acc[nt][1] = 0.f; acc[nt][2] = 0.f; acc[nt][3] = 0.f;
        }

        #pragma unroll
        for (int ks = 0; ks < 4; ks++) {
            const int c0 = ks * 16 + 4 * tg;
            // row r0: float4 -> (x,y)=a0 pair, (z,w)=a2 pair
            float4 A0 = *(const float4*)(p0a + c0);
            float4 A1 = *(const float4*)(p1a + c0);
            if (EDGE) {
                float4 B0 = *(const float4*)(p0b + c0);
                float4 B1 = *(const float4*)(p1b + c0);
                A0.x = fmaxf(A0.x + B0.x, 0.f); A0.y = fmaxf(A0.y + B0.y, 0.f);
                A0.z = fmaxf(A0.z + B0.z, 0.f); A0.w = fmaxf(A0.w + B0.w, 0.f);
                A1.x = fmaxf(A1.x + B1.x, 0.f); A1.y = fmaxf(A1.y + B1.y, 0.f);
                A1.z = fmaxf(A1.z + B1.z, 0.f); A1.w = fmaxf(A1.w + B1.w, 0.f);
            }
            uint32_t ahi[4], alo[4];
            ahi[0] = bf2(A0.x, A0.y);  alo[0] = bf2lo(ahi[0], A0.x, A0.y);
            ahi[1] = bf2(A1.x, A1.y);  alo[1] = bf2lo(ahi[1], A1.x, A1.y);
            ahi[2] = bf2(A0.z, A0.w);  alo[2] = bf2lo(ahi[2], A0.z, A0.w);
            ahi[3] = bf2(A1.z, A1.w);  alo[3] = bf2lo(ahi[3], A1.z, A1.w);

            #pragma unroll
            for (int nt = 0; nt < 8; nt++) {
                mma_bf16(acc[nt], ahi, Bhi[nt][ks]);
                mma_bf16(acc[nt], alo, Bhi[nt][ks]);
                mma_bf16(acc[nt], ahi, Blo[nt][ks]);
            }
        }

        float* o0 = out + (long long)r0 * DIM;
        float* o1 = out + (long long)r1 * DIM;
        #pragma unroll
        for (int nt = 0; nt < 8; nt++) {
            float2 bb = *(const float2*)(bias + nt * 8 + 2 * tg);
            float2 v0 = make_float2(SC * acc[nt][0] + 0.5f * bb.x,
                                    SC * acc[nt][1] + 0.5f * bb.y);
            float2 v1 = make_float2(SC * acc[nt][2] + 0.5f * bb.x,
                                    SC * acc[nt][3] + 0.5f * bb.y);
            if (EDGE) {
                __stcs((float2*)(o0 + nt * 8 + 2 * tg), v0);
                __stcs((float2*)(o1 + nt * 8 + 2 * tg), v1);
            } else {
                *(float2*)(o0 + nt * 8 + 2 * tg) = v0;
                *(float2*)(o1 + nt * 8 + 2 * tg) = v1;
            }
        }
    }
}

// ---------------- launch ----------------
extern "C" void kernel_launch(void* const* d_in, const int* in_sizes, int n_in,
                              void* d_out, int out_size) {
    const float4* edge_feat = (const float4*)d_in[0];
    const void*   src       = d_in[1];
    const void*   dst       = d_in[2];
    const float*  W1        = (const float*)d_in[3];
    const float*  b1        = (const float*)d_in[4];
    const float*  W2        = (const float*)d_in[5];
    const float*  b2        = (const float*)d_in[6];
    float*        out       = (float*)d_out;

    zero_detect_kernel<<<(NNODES * DIM / 4 + 255) / 256, 256>>>((const int*)src);
    scatter_kernel<<<(NEDGES * 16 + 255) / 256, 256>>>(edge_feat, dst);
    mlp_kernel<false><<<148, 256>>>(nullptr, nullptr, W1, b1, nullptr, NTILES);
    mlp_kernel<true><<<148, 256>>>(src, dst, W2, b2, out, ETILES);
}

// round 16
// speedup vs baseline: 1.7418x; 1.0121x over previous
#include <cuda_runtime.h>
#include <cuda_bf16.h>
#include <cstdint>
#include <cstddef>

#define NNODES 50000
#define NEDGES 800000
#define DIM 64
#define ETILES (NEDGES / 16)    // 50000
#define NTILES (NNODES / 16)    // 3125
#define ROWB 272                // padded row stride in smem (256B data + 16B pad)
#define STAGEB (32 * ROWB)      // 8704 B per stage per warp
#define WARPB (2 * STAGEB)      // 17408 B per warp
#define EDGE_SMEM (8 * WARPB)   // 139264 B per 256-thread block

__device__ float g_node_x[NNODES * DIM];
__device__ float g_y[NNODES * DIM];      // node_x @ W1 + 0.5*b1
__device__ int   g_is64;

// pack two fp32 -> bf16x2
__device__ __forceinline__ uint32_t bf2(float lo, float hi) {
    uint32_t r;
    asm("cvt.rn.bf16x2.f32 %0, %1, %2;" : "=r"(r) : "f"(hi), "f"(lo));
    return r;
}
__device__ __forceinline__ uint32_t bf2lo(uint32_t h, float x, float y) {
    return bf2(x - __uint_as_float(h << 16), y - __uint_as_float(h & 0xFFFF0000u));
}
__device__ __forceinline__ void mma_bf16(float* d, const uint32_t* a, const uint32_t* b) {
    asm volatile(
        "mma.sync.aligned.m16n8k16.row.col.f32.bf16.bf16.f32 "
        "{%0,%1,%2,%3}, {%4,%5,%6,%7}, {%8,%9}, {%0,%1,%2,%3};"
        : "+f"(d[0]), "+f"(d[1]), "+f"(d[2]), "+f"(d[3])
        : "r"(a[0]), "r"(a[1]), "r"(a[2]), "r"(a[3]), "r"(b[0]), "r"(b[1]));
}
__device__ __forceinline__ long long load_idx(const void* p, int e, int is64) {
    return is64 ? ((const long long*)p)[e] : (long long)((const int*)p)[e];
}

// ---------------- fused zero + dtype-detect ----------------
__global__ void zero_detect_kernel(const int* __restrict__ src) {
    int i = blockIdx.x * blockDim.x + threadIdx.x;
    if (i < NNODES * DIM / 4)
        ((float4*)g_node_x)[i] = make_float4(0.f, 0.f, 0.f, 0.f);
    if (i == 0) {
        int z = 1;
        #pragma unroll
        for (int k = 0; k < 32; k++) z &= (src[2 * k + 1] == 0);
        g_is64 = z;
    }
}

// ---------------- scatter: node_x[dst] += edge_feat ----------------
__global__ void scatter_kernel(const float4* __restrict__ ef, const void* __restrict__ dstp) {
    int t = blockIdx.x * blockDim.x + threadIdx.x;
    if (t >= NEDGES * (DIM / 4)) return;
    int e = t >> 4;
    int q = t & 15;
    long long d = g_is64 ? ((const long long*)dstp)[e]
                         : (long long)((const int*)dstp)[e];
    float4 v = __ldcs(ef + t);
    float* addr = g_node_x + d * DIM + q * 4;
    asm volatile("red.global.add.v4.f32 [%0], {%1, %2, %3, %4};"
                 :: "l"(addr), "f"(v.x), "f"(v.y), "f"(v.z), "f"(v.w) : "memory");
}

// ---------------- cp.async gather of one tile's 32 rows into smem ----------------
// lane l holds rowidx: l<16 -> src node of edge l, l>=16 -> dst node of edge l-16.
// chunk c = lane + 32*i: row = c>>4, quad = c&15.
__device__ __forceinline__ void cp_tile(uint32_t sbase, int myidx, int lane) {
    #pragma unroll
    for (int i = 0; i < 16; i++) {
        int c = lane + 32 * i;
        int row = c >> 4, q = c & 15;
        int idx = __shfl_sync(0xFFFFFFFFu, myidx, row);
        const char* srcp = (const char*)(g_y + (long long)idx * DIM) + q * 16;
        uint32_t dst = sbase + row * ROWB + q * 16;
        asm volatile("cp.async.cg.shared.global [%0], [%1], 16;" :: "r"(dst), "l"(srcp));
    }
    asm volatile("cp.async.commit_group;" ::: "memory");
}
__device__ __forceinline__ int tile_idx(const void* srcp, const void* dstp,
                                        int tile, int lane, int is64) {
    int e = tile * 16 + (lane & 15);
    return (int)load_idx(lane < 16 ? srcp : dstp, e, is64);
}

// ---------------- HMMA MLP kernel (k-permuted; EDGE uses cp.async pipeline) ----------------
// EDGE=false: y[row]   = node_x[row] @ W1 + 0.5*b1
// EDGE=true : out[row] = 0.5*(relu(y[src]+y[dst]) @ W2) + 0.5*b2
template <bool EDGE>
__global__ void __launch_bounds__(256, 1) mlp_kernel(
    const void* __restrict__ srcp, const void* __restrict__ dstp,
    const float* __restrict__ W, const float* __restrict__ bias,
    float* __restrict__ outp, int ntiles)
{
    extern __shared__ char dsm[];
    const int tid = threadIdx.x;
    const int warp = tid >> 5, lane = tid & 31;
    const int g = lane >> 2, tg = lane & 3;
    const int is64 = EDGE ? g_is64 : 0;
    float* __restrict__ out = EDGE ? outp : g_y;
    constexpr float SC = EDGE ? 0.5f : 1.0f;

    // B fragments with permuted k: slot pair (2t+8hx) <- W rows (ks*16 + 4*tg + 2*hx, +1)
    uint32_t Bhi[8][4][2], Blo[8][4][2];
    #pragma unroll
    for (int nt = 0; nt < 8; nt++) {
        int n = nt * 8 + g;
        #pragma unroll
        for (int ks = 0; ks < 4; ks++) {
            #pragma unroll
            for (int hx = 0; hx < 2; hx++) {
                int k = ks * 16 + 4 * tg + 2 * hx;
                float w0 = W[k * DIM + n];
                float w1 = W[(k + 1) * DIM + n];
                uint32_t h = bf2(w0, w1);
                Bhi[nt][ks][hx] = h;
                Blo[nt][ks][hx] = bf2lo(h, w0, w1);
            }
        }
    }

    const int gw = blockIdx.x * 8 + warp;
    const int nw = gridDim.x * 8;
    if (gw >= ntiles) return;

    uint32_t wbase = 0;
    int nextidx = 0;
    if (EDGE) {
        wbase = (uint32_t)__cvta_generic_to_shared(dsm + warp * WARPB);
        int myidx = tile_idx(srcp, dstp, gw, lane, is64);
        cp_tile(wbase, myidx, lane);                    // stage 0 <- tile gw
        int tn = gw + nw;
        nextidx = tile_idx(srcp, dstp, tn < ntiles ? tn : gw, lane, is64);
    }

    int stage = 0;
    for (int tile = gw; tile < ntiles; tile += nw) {
        const int r0 = tile * 16 + g;
        const int r1 = r0 + 8;

        if (EDGE) {
            // issue next tile's gathers into the other stage
            cp_tile(wbase + (stage ^ 1) * STAGEB, nextidx, lane);
            // prefetch indices for tile after next
            const int t2 = tile + 2 * nw;
            if (t2 < ntiles) nextidx = tile_idx(srcp, dstp, t2, lane, is64);
            // wait for current tile's data (own older group), then warp-sync
            asm volatile("cp.async.wait_group 1;" ::: "memory");
            __syncwarp();
        }

        float acc[8][4];
        #pragma unroll
        for (int nt = 0; nt < 8; nt++) {
            acc[nt][0] = 0.f; acc[nt][1] = 0.f; acc[nt][2] = 0.f; acc[nt][3] = 0.f;
        }

        const char* sb = EDGE ? (dsm + warp * WARPB + stage * STAGEB) : nullptr;
        const float* p0a = nullptr; const float* p1a = nullptr;
        if (!EDGE) {
            p0a = g_node_x + (long long)r0 * DIM;
            p1a = g_node_x + (long long)r1 * DIM;
        }

        #pragma unroll
        for (int ks = 0; ks < 4; ks++) {
            const int cb = ks * 64 + tg * 16;       // byte offset within row
            float4 A0, A1;
            if (EDGE) {
                // rows: src edge g -> row g; src edge g+8 -> row g+8;
                //       dst edge g -> row 16+g; dst edge g+8 -> row 24+g
                float4 S0 = *(const float4*)(sb + (g)      * ROWB + cb);
                float4 S1 = *(const float4*)(sb + (g + 8)  * ROWB + cb);
                float4 D0 = *(const float4*)(sb + (16 + g) * ROWB + cb);
                float4 D1 = *(const float4*)(sb + (24 + g) * ROWB + cb);
                A0.x = fmaxf(S0.x + D0.x, 0.f); A0.y = fmaxf(S0.y + D0.y, 0.f);
                A0.z = fmaxf(S0.z + D0.z, 0.f); A0.w = fmaxf(S0.w + D0.w, 0.f);
                A1.x = fmaxf(S1.x + D1.x, 0.f); A1.y = fmaxf(S1.y + D1.y, 0.f);
                A1.z = fmaxf(S1.z + D1.z, 0.f); A1.w = fmaxf(S1.w + D1.w, 0.f);
            } else {
                A0 = *(const float4*)((const char*)p0a + cb);
                A1 = *(const float4*)((const char*)p1a + cb);
            }
            uint32_t ahi[4], alo[4];
            ahi[0] = bf2(A0.x, A0.y);  alo[0] = bf2lo(ahi[0], A0.x, A0.y);
            ahi[1] = bf2(A1.x, A1.y);  alo[1] = bf2lo(ahi[1], A1.x, A1.y);
            ahi[2] = bf2(A0.z, A0.w);  alo[2] = bf2lo(ahi[2], A0.z, A0.w);
            ahi[3] = bf2(A1.z, A1.w);  alo[3] = bf2lo(ahi[3], A1.z, A1.w);

            #pragma unroll
            for (int nt = 0; nt < 8; nt++) {
                mma_bf16(acc[nt], ahi, Bhi[nt][ks]);
                mma_bf16(acc[nt], alo, Bhi[nt][ks]);
                mma_bf16(acc[nt], ahi, Blo[nt][ks]);
            }
        }

        float* o0 = out + (long long)r0 * DIM;
        float* o1 = out + (long long)r1 * DIM;
        #pragma unroll
        for (int nt = 0; nt < 8; nt++) {
            float2 bb = *(const float2*)(bias + nt * 8 + 2 * tg);
            float2 v0 = make_float2(SC * acc[nt][0] + 0.5f * bb.x,
                                    SC * acc[nt][1] + 0.5f * bb.y);
            float2 v1 = make_float2(SC * acc[nt][2] + 0.5f * bb.x,
                                    SC * acc[nt][3] + 0.5f * bb.y);
            if (EDGE) {
                __stcs((float2*)(o0 + nt * 8 + 2 * tg), v0);
                __stcs((float2*)(o1 + nt * 8 + 2 * tg), v1);
            } else {
                *(float2*)(o0 + nt * 8 + 2 * tg) = v0;
                *(float2*)(o1 + nt * 8 + 2 * tg) = v1;
            }
        }
        stage ^= 1;
    }
}

// ---------------- launch ----------------
extern "C" void kernel_launch(void* const* d_in, const int* in_sizes, int n_in,
                              void* d_out, int out_size) {
    const float4* edge_feat = (const float4*)d_in[0];
    const void*   src       = d_in[1];
    const void*   dst       = d_in[2];
    const float*  W1        = (const float*)d_in[3];
    const float*  b1        = (const float*)d_in[4];
    const float*  W2        = (const float*)d_in[5];
    const float*  b2        = (const float*)d_in[6];
    float*        out       = (float*)d_out;

    cudaFuncSetAttribute(mlp_kernel<true>, cudaFuncAttributeMaxDynamicSharedMemorySize, EDGE_SMEM);

    zero_detect_kernel<<<(NNODES * DIM / 4 + 255) / 256, 256>>>((const int*)src);
    scatter_kernel<<<(NEDGES * 16 + 255) / 256, 256>>>(edge_feat, dst);
    mlp_kernel<false><<<148, 256, 0>>>(nullptr, nullptr, W1, b1, nullptr, NTILES);
    mlp_kernel<true><<<148, 256, EDGE_SMEM>>>(src, dst, W2, b2, out, ETILES);
}